// round 15
// baseline (speedup 1.0000x reference)
#include <cuda_runtime.h>
#include <cuda_fp16.h>
#include <stdint.h>

#define DD 512
#define HH 1024
#define NTOK 4096
#define SS 2
#define GG 2
#define NGR 6
#define CC 32
#define KK 3
#define NEVT 50
#define BM 128
#define BN 128
#define BK 32
#define MAXTILES 40
#define NBANK (SS + NGR * GG)
#define NSHT (NTOK / BM)
#define LDHB 80
#define ARRB 10240
#define STAGEB (4 * ARRB)
#define NSTAGE 2
#define SMEM_TOT (NSTAGE * STAGEB)   // 81920 -> 2 CTAs/SM

// hi/lo halves live in ONE array: [hi | lo], lo at constant element offset.
#define XLO   (NTOK * DD)
#define W1LO  (NBANK * HH * DD)
#define W2LO  (NBANK * DD * HH)
#define HSLO  (NTOK * SS * HH)
#define HGLO  (NTOK * GG * HH)

__device__ __align__(16) __half gxA[2 * NTOK * DD];
__device__ __align__(16) __half gw1A[2 * NBANK * HH * DD];   // [bank][N][K]
__device__ __align__(16) __half gw2A[2 * NBANK * DD * HH];
__device__ __align__(16) __half gh1sA[2 * NTOK * SS * HH];
__device__ __align__(16) __half gh1gA[2 * NTOK * GG * HH];
__device__ __align__(16) float g_outs[NTOK * SS * DD], g_outg[NTOK * GG * DD];
__device__ int g_gid[NTOK], g_perm[NTOK];
__device__ int g_tile_group[MAXTILES], g_tile_m0[MAXTILES], g_tile_end[MAXTILES], g_ntiles;

// ---------------- PTX helpers ------------------------------------------------
__device__ __forceinline__ void cp16(uint32_t d, const void* s, bool v) {
    int sz = v ? 16 : 0;
    asm volatile("cp.async.cg.shared.global [%0], [%1], 16, %2;" :: "r"(d), "l"(s), "r"(sz));
}
#define CPC() asm volatile("cp.async.commit_group;")
#define CPW(N) asm volatile("cp.async.wait_group %0;" :: "n"(N))
#define LDSM4(r, a) asm volatile("ldmatrix.sync.aligned.m8n8.x4.shared.b16 {%0,%1,%2,%3}, [%4];" \
    : "=r"((r)[0]), "=r"((r)[1]), "=r"((r)[2]), "=r"((r)[3]) : "r"(a))
#define MMA16(d, a, b) asm volatile( \
    "mma.sync.aligned.m16n8k16.row.col.f32.f16.f16.f32 " \
    "{%0,%1,%2,%3}, {%4,%5,%6,%7}, {%8,%9}, {%0,%1,%2,%3};" \
    : "+f"((d)[0]), "+f"((d)[1]), "+f"((d)[2]), "+f"((d)[3]) \
    : "r"((a)[0]), "r"((a)[1]), "r"((a)[2]), "r"((a)[3]), "r"((b)[0]), "r"((b)[1]))

// ---------------- prep -------------------------------------------------------
__global__ void k_prep(const int* __restrict__ nti, const int* __restrict__ e2g) {
    __shared__ int cnt[NGR], st[NGR], cur[NGR];
    int t = threadIdx.x;
    if (t < NGR) cnt[t] = 0;
    __syncthreads();
    for (int n = t; n < NTOK; n += blockDim.x) {
        int v = nti[n]; v = v < 0 ? 0 : (v > NEVT - 1 ? NEVT - 1 : v);
        int g = e2g[v]; g_gid[n] = g; atomicAdd(&cnt[g], 1);
    }
    __syncthreads();
    if (t == 0) {
        int acc = 0, ntl = 0;
        for (int g = 0; g < NGR; g++) {
            st[g] = acc; int c = cnt[g];
            for (int m0 = acc; m0 < acc + c; m0 += BM) {
                g_tile_group[ntl] = g; g_tile_m0[ntl] = m0; g_tile_end[ntl] = acc + c; ntl++;
            }
            acc += c;
        }
        g_ntiles = ntl;
        for (int g = 0; g < NGR; g++) cur[g] = st[g];
    }
    __syncthreads();
    for (int n = t; n < NTOK; n += blockDim.x) {
        int pos = atomicAdd(&cur[g_gid[n]], 1);
        g_perm[pos] = n;
    }
}

// ---------------- split x ----------------------------------------------------
__global__ void k_cvt_x(const float4* __restrict__ x) {
    int i = blockIdx.x * 256 + threadIdx.x;
    float4 v = x[i];
    __half h0 = __float2half_rn(v.x), h1 = __float2half_rn(v.y);
    __half h2 = __float2half_rn(v.z), h3 = __float2half_rn(v.w);
    __half2 H0; H0.x = h0; H0.y = h1;
    __half2 H1; H1.x = h2; H1.y = h3;
    __half2 L0, L1;
    L0.x = __float2half_rn(v.x - __half2float(h0));
    L0.y = __float2half_rn(v.y - __half2float(h1));
    L1.x = __float2half_rn(v.z - __half2float(h2));
    L1.y = __float2half_rn(v.w - __half2float(h3));
    __half2* hp = reinterpret_cast<__half2*>(gxA);
    hp[2 * i] = H0;
    hp[2 * i + 1] = H1;
    hp[XLO / 2 + 2 * i] = L0;
    hp[XLO / 2 + 2 * i + 1] = L1;
}

// weight convert+transpose: z<SS shared bank, else grouped.
template <int LAYER>
__global__ void __launch_bounds__(256)
k_cvt_w(const float* __restrict__ srcS, const float* __restrict__ srcG) {
    const int Kd = (LAYER == 1) ? DD : HH;
    const int Nd = (LAYER == 1) ? HH : DD;
    const int WLO2 = ((LAYER == 1) ? W1LO : W2LO) / 2;
    __shared__ float s[64][65];
    int z = blockIdx.z, k0 = blockIdx.x * 64, n0 = blockIdx.y * 64;
    const float* sp = (z < SS) ? srcS + (size_t)z * Kd * Nd
                               : srcG + (size_t)(z - SS) * Kd * Nd;
    int t = threadIdx.x;
    int r = t >> 4, c4 = (t & 15) * 4;
#pragma unroll
    for (int i = 0; i < 4; i++) {
        float4 v = *reinterpret_cast<const float4*>(
            sp + (size_t)(k0 + r + 16 * i) * Nd + n0 + c4);
        s[r + 16 * i][c4 + 0] = v.x;
        s[r + 16 * i][c4 + 1] = v.y;
        s[r + 16 * i][c4 + 2] = v.z;
        s[r + 16 * i][c4 + 3] = v.w;
    }
    __syncthreads();
    __half2* dst = reinterpret_cast<__half2*>((LAYER == 1) ? gw1A : gw2A);
    int tx = t & 31, ny = t >> 5;
#pragma unroll
    for (int i = 0; i < 8; i++) {
        int nl = ny * 8 + i;
        float v0 = s[2 * tx][nl], v1 = s[2 * tx + 1][nl];
        __half h0 = __float2half_rn(v0), h1 = __float2half_rn(v1);
        __half2 H; H.x = h0; H.y = h1;
        __half2 L;
        L.x = __float2half_rn(v0 - __half2float(h0));
        L.y = __float2half_rn(v1 - __half2float(h1));
        size_t o = (((size_t)z * Nd + n0 + nl) * Kd + k0) / 2 + tx;
        dst[o] = H;
        dst[WLO2 + o] = L;
    }
}

// ---------------- fp16x3 tensor GEMM -----------------------------------------
// D += Ah*Bh + Ah*Bl + Al*Bh (fp32 accum). Sequential passes to cap frag regs.
template <int LAYER>
__global__ void __launch_bounds__(256, 2)
k_mma(const float* __restrict__ bias_s, const float* __restrict__ bias_g) {
    const int KTOT = (LAYER == 1) ? DD : HH;
    const int WLO = (LAYER == 1) ? W1LO : W2LO;
    bool grouped;
    int m0, mend, g = 0;
    if ((int)blockIdx.x < NSHT) {
        grouped = false; m0 = blockIdx.x * BM; mend = NTOK;
    } else {
        grouped = true;
        int tile = blockIdx.x - NSHT;
        if (tile >= g_ntiles) return;
        g = g_tile_group[tile]; m0 = g_tile_m0[tile]; mend = g_tile_end[tile];
    }
    const int colstart = blockIdx.y * BN;

    extern __shared__ char dsm[];
    const uint32_t base = (uint32_t)__cvta_generic_to_shared(dsm);

    const int tid = threadIdx.x;
    const int lane = tid & 31;
    const int warp = tid >> 5;
    const int wm = warp >> 2;
    const int wn = warp & 3;

    int bias_off, seg;
    const __half* wH;
    const float* bias;
    if (LAYER == 1) {
        seg = colstart >> 10;
        int bank = grouped ? (SS + g * GG + seg) : seg;
        wH = gw1A + ((size_t)bank * HH + (colstart & (HH - 1))) * DD;
        bias_off = grouped ? g * (GG * HH) + colstart : colstart;
    } else {
        seg = colstart >> 9;
        int bank = grouped ? (SS + g * GG + seg) : seg;
        wH = gw2A + ((size_t)bank * DD + (colstart & (DD - 1))) * HH;
        bias_off = grouped ? g * (GG * DD) + colstart : colstart;
    }
    bias = grouped ? bias_g : bias_s;

    const int r0 = tid >> 2, r1 = 64 + (tid >> 2);
    const uint32_t cb = (uint32_t)(tid & 3) * 16;
    const uint32_t o0 = (uint32_t)r0 * LDHB + cb, o1 = (uint32_t)r1 * LDHB + cb;
    const int kadd = (tid & 3) * 8;

    const __half *pa0, *pa1;
    size_t aLo;
    bool v0 = true, v1 = true;
    {
        int p0 = m0 + r0, p1 = m0 + r1;
        if (LAYER == 1) {
            aLo = XLO;
            if (!grouped) {
                pa0 = gxA + (size_t)p0 * DD;
                pa1 = gxA + (size_t)p1 * DD;
            } else {
                v0 = p0 < mend; v1 = p1 < mend;
                pa0 = gxA + (size_t)(v0 ? g_perm[p0] : 0) * DD;
                pa1 = gxA + (size_t)(v1 ? g_perm[p1] : 0) * DD;
            }
        } else {
            if (!grouped) {
                aLo = HSLO;
                pa0 = gh1sA + (size_t)p0 * (SS * HH) + seg * HH;
                pa1 = gh1sA + (size_t)p1 * (SS * HH) + seg * HH;
            } else {
                aLo = HGLO;
                v0 = p0 < mend; v1 = p1 < mend;
                pa0 = gh1gA + (size_t)(v0 ? p0 : 0) * (GG * HH) + seg * HH;
                pa1 = gh1gA + (size_t)(v1 ? p1 : 0) * (GG * HH) + seg * HH;
            }
        }
    }
    const __half* pb0 = wH + (size_t)r0 * KTOT;
    const __half* pb1 = wH + (size_t)r1 * KTOT;

    // stage layout: [Ah][Al][Bh][Bl]
    auto load = [&](int buf, int it) {
        uint32_t sB = base + buf * STAGEB;
        int ke = it * BK + kadd;
        const __half* a0 = pa0 + ke;
        const __half* a1 = pa1 + ke;
        const __half* b0 = pb0 + ke;
        const __half* b1 = pb1 + ke;
        cp16(sB + o0, a0, v0);
        cp16(sB + o1, a1, v1);
        cp16(sB + ARRB + o0, a0 + aLo, v0);
        cp16(sB + ARRB + o1, a1 + aLo, v1);
        cp16(sB + 2 * ARRB + o0, b0, true);
        cp16(sB + 2 * ARRB + o1, b1, true);
        cp16(sB + 3 * ARRB + o0, b0 + WLO, true);
        cp16(sB + 3 * ARRB + o1, b1 + WLO, true);
        CPC();
    };

    float d[4][4][4];
#pragma unroll
    for (int i = 0; i < 4; i++)
#pragma unroll
        for (int j = 0; j < 4; j++)
#pragma unroll
            for (int q = 0; q < 4; q++) d[i][j][q] = 0.f;

    const int NIT = KTOT / BK;
    load(0, 0);

    for (int it = 0; it < NIT; it++) {
        const int buf = it & 1;
        if (it + 1 < NIT) { load(buf ^ 1, it + 1); CPW(1); }
        else CPW(0);
        __syncthreads();
        const uint32_t sB = base + buf * STAGEB;

#pragma unroll
        for (int ks = 0; ks < 2; ks++) {
            const uint32_t colb = (uint32_t)((ks * 16 + ((lane >> 4) << 3)) << 1);
            uint32_t af[4][4], bh[4][2], bx[4][2];
            const uint32_t aAddr = sB + (uint32_t)(wm * 64 + (lane & 15)) * LDHB + colb;
            const uint32_t bAddr = sB + 2 * ARRB + (uint32_t)(wn * 32 + (lane & 15)) * LDHB + colb;
            // load Ah + Bh + Bl
#pragma unroll
            for (int mt = 0; mt < 4; mt++) LDSM4(af[mt], aAddr + (uint32_t)(mt * 16) * LDHB);
#pragma unroll
            for (int np = 0; np < 2; np++) {
                uint32_t q[4];
                LDSM4(q, bAddr + (uint32_t)(np * 16) * LDHB);
                bh[np * 2][0] = q[0]; bh[np * 2][1] = q[2];
                bh[np * 2 + 1][0] = q[1]; bh[np * 2 + 1][1] = q[3];
                LDSM4(q, bAddr + (uint32_t)(np * 16) * LDHB + ARRB);
                bx[np * 2][0] = q[0]; bx[np * 2][1] = q[2];
                bx[np * 2 + 1][0] = q[1]; bx[np * 2 + 1][1] = q[3];
            }
            // pass1: Ah*Bh   pass2: Ah*Bl
#pragma unroll
            for (int mt = 0; mt < 4; mt++)
#pragma unroll
                for (int nt = 0; nt < 4; nt++) MMA16(d[mt][nt], af[mt], bh[nt]);
#pragma unroll
            for (int mt = 0; mt < 4; mt++)
#pragma unroll
                for (int nt = 0; nt < 4; nt++) MMA16(d[mt][nt], af[mt], bx[nt]);
            // reload frags with Al, pass3: Al*Bh
#pragma unroll
            for (int mt = 0; mt < 4; mt++) LDSM4(af[mt], aAddr + (uint32_t)(mt * 16) * LDHB + ARRB);
#pragma unroll
            for (int mt = 0; mt < 4; mt++)
#pragma unroll
                for (int nt = 0; nt < 4; nt++) MMA16(d[mt][nt], af[mt], bh[nt]);
        }
        __syncthreads();
    }

    // ---- epilogue ----
    float bb0[4], bb1[4];
#pragma unroll
    for (int nt = 0; nt < 4; nt++) {
        int cbx = wn * 32 + nt * 8 + 2 * (lane & 3);
        bb0[nt] = bias[bias_off + cbx];
        bb1[nt] = bias[bias_off + cbx + 1];
    }

#pragma unroll
    for (int mt = 0; mt < 4; mt++) {
#pragma unroll
        for (int half = 0; half < 2; half++) {
            int p = m0 + wm * 64 + mt * 16 + (lane >> 2) + half * 8;
            if (grouped && p >= mend) continue;
            if (LAYER == 1) {
                __half* dh;
                size_t hLo;
                if (!grouped) {
                    dh = gh1sA + (size_t)p * (SS * HH) + colstart;
                    hLo = HSLO;
                } else {
                    dh = gh1gA + (size_t)p * (GG * HH) + colstart;
                    hLo = HGLO;
                }
#pragma unroll
                for (int nt = 0; nt < 4; nt++) {
                    int cbx = wn * 32 + nt * 8 + 2 * (lane & 3);
                    float u0 = d[mt][nt][half * 2 + 0] + bb0[nt];
                    float u1 = d[mt][nt][half * 2 + 1] + bb1[nt];
                    u0 = u0 > 0.f ? u0 : 0.f;
                    u1 = u1 > 0.f ? u1 : 0.f;
                    __half h0 = __float2half_rn(u0), h1 = __float2half_rn(u1);
                    __half2 H; H.x = h0; H.y = h1;
                    __half2 L;
                    L.x = __float2half_rn(u0 - __half2float(h0));
                    L.y = __float2half_rn(u1 - __half2float(h1));
                    *reinterpret_cast<__half2*>(dh + cbx) = H;
                    *reinterpret_cast<__half2*>(dh + hLo + cbx) = L;
                }
            } else {
                float* dst = (!grouped) ? g_outs + (size_t)p * (SS * DD) + colstart
                                        : g_outg + (size_t)g_perm[p] * (GG * DD) + colstart;
#pragma unroll
                for (int nt = 0; nt < 4; nt++) {
                    int cbx = wn * 32 + nt * 8 + 2 * (lane & 3);
                    float u0 = d[mt][nt][half * 2 + 0] + bb0[nt];
                    float u1 = d[mt][nt][half * 2 + 1] + bb1[nt];
                    *reinterpret_cast<float2*>(dst + cbx) = make_float2(u0, u1);
                }
            }
        }
    }
}

// ---------------- gate + combine ---------------------------------------------
__global__ void k_gate(const float* __restrict__ x, const float* __restrict__ cond_emb,
                       const float* __restrict__ gate_W, const float* __restrict__ gate_b,
                       float* __restrict__ out) {
    const int n = blockIdx.x;
    const int FD = DD + CC;
    __shared__ float gx[DD + CC], lg[KK * 4], w[KK * 4];
    const int t = threadIdx.x;
    const float* xr = x + (size_t)n * DD;
    for (int i = t; i < DD; i += 128) gx[i] = xr[i];
    if (t < CC) gx[DD + t] = cond_emb[g_gid[n] * CC + t];
    __syncthreads();
    const int warp = t >> 5, lane = t & 31, p0 = warp * 3;
    float s0 = 0.f, s1 = 0.f, s2 = 0.f;
    for (int f = lane; f < FD; f += 32) {
        float xv = gx[f];
        int p;
        p = p0 + 0; s0 = fmaf(xv, gate_W[((p >> 2) * FD + f) * 4 + (p & 3)], s0);
        p = p0 + 1; s1 = fmaf(xv, gate_W[((p >> 2) * FD + f) * 4 + (p & 3)], s1);
        p = p0 + 2; s2 = fmaf(xv, gate_W[((p >> 2) * FD + f) * 4 + (p & 3)], s2);
    }
#pragma unroll
    for (int o = 16; o > 0; o >>= 1) {
        s0 += __shfl_down_sync(0xffffffffu, s0, o);
        s1 += __shfl_down_sync(0xffffffffu, s1, o);
        s2 += __shfl_down_sync(0xffffffffu, s2, o);
    }
    if (lane == 0) {
        lg[p0 + 0] = s0 + gate_b[p0 + 0];
        lg[p0 + 1] = s1 + gate_b[p0 + 1];
        lg[p0 + 2] = s2 + gate_b[p0 + 2];
    }
    __syncthreads();
    if (t < KK) {
        float l0 = lg[t * 4], l1 = lg[t * 4 + 1], l2 = lg[t * 4 + 2], l3 = lg[t * 4 + 3];
        float m = fmaxf(fmaxf(l0, l1), fmaxf(l2, l3));
        float e0 = expf(l0 - m), e1 = expf(l1 - m), e2 = expf(l2 - m), e3 = expf(l3 - m);
        float inv = 1.f / (e0 + e1 + e2 + e3);
        w[t * 4] = e0 * inv; w[t * 4 + 1] = e1 * inv;
        w[t * 4 + 2] = e2 * inv; w[t * 4 + 3] = e3 * inv;
    }
    __syncthreads();
    const float4* so4 = reinterpret_cast<const float4*>(g_outs + (size_t)n * (SS * DD));
    const float4* go4 = reinterpret_cast<const float4*>(g_outg + (size_t)n * (GG * DD));
    {
        float4 e0 = so4[t], e1 = so4[DD / 4 + t], e2 = go4[t], e3 = go4[DD / 4 + t];
#pragma unroll
        for (int k = 0; k < KK; k++) {
            float w0 = w[k * 4], w1 = w[k * 4 + 1], w2 = w[k * 4 + 2], w3 = w[k * 4 + 3];
            float4 r;
            r.x = w0 * e0.x + w1 * e1.x + w2 * e2.x + w3 * e3.x;
            r.y = w0 * e0.y + w1 * e1.y + w2 * e2.y + w3 * e3.y;
            r.z = w0 * e0.z + w1 * e1.z + w2 * e2.z + w3 * e3.z;
            r.w = w0 * e0.w + w1 * e1.w + w2 * e2.w + w3 * e3.w;
            reinterpret_cast<float4*>(out)[((size_t)k * NTOK + n) * (DD / 4) + t] = r;
        }
    }
}

// ---------------- launch ------------------------------------------------------
extern "C" void kernel_launch(void* const* d_in, const int* in_sizes, int n_in,
                              void* d_out, int out_size) {
    const float* x   = (const float*)d_in[0];
    const int* nti   = (const int*)d_in[1];
    const int* e2g   = (const int*)d_in[2];
    const float* Ws1 = (const float*)d_in[3];
    const float* bs1 = (const float*)d_in[4];
    const float* Ws2 = (const float*)d_in[5];
    const float* bs2 = (const float*)d_in[6];
    const float* Wg1 = (const float*)d_in[7];
    const float* bg1 = (const float*)d_in[8];
    const float* Wg2 = (const float*)d_in[9];
    const float* bg2 = (const float*)d_in[10];
    const float* cemb = (const float*)d_in[11];
    const float* gW  = (const float*)d_in[12];
    const float* gb  = (const float*)d_in[13];
    float* out = (float*)d_out;

    cudaFuncSetAttribute(k_mma<1>, cudaFuncAttributeMaxDynamicSharedMemorySize, SMEM_TOT);
    cudaFuncSetAttribute(k_mma<2>, cudaFuncAttributeMaxDynamicSharedMemorySize, SMEM_TOT);

    k_prep<<<1, 256>>>(nti, e2g);
    k_cvt_x<<<NTOK * DD / 4 / 256, 256>>>((const float4*)x);
    k_cvt_w<1><<<dim3(DD / 64, HH / 64, NBANK), 256>>>(Ws1, Wg1);
    k_cvt_w<2><<<dim3(HH / 64, DD / 64, NBANK), 256>>>(Ws2, Wg2);
    k_mma<1><<<dim3(NSHT + MAXTILES, (SS * HH) / BN), 256, SMEM_TOT>>>(bs1, bg1);
    k_mma<2><<<dim3(NSHT + MAXTILES, (SS * DD) / BN), 256, SMEM_TOT>>>(bs2, bg2);
    k_gate<<<NTOK, 128>>>(x, cemb, gW, gb, out);
}

// round 16
// speedup vs baseline: 1.0185x; 1.0185x over previous
#include <cuda_runtime.h>
#include <cuda_fp16.h>
#include <stdint.h>

#define DD 512
#define HH 1024
#define NTOK 4096
#define SS 2
#define GG 2
#define NGR 6
#define CC 32
#define KK 3
#define NEVT 50
#define BM 128
#define BN 128
#define BK 32
#define MAXTILES 40
#define NBANK (SS + NGR * GG)
#define NSHT (NTOK / BM)
#define LDHB 80
#define ARRB 10240
#define STAGEB (4 * ARRB)
#define NSTAGE 2
#define SMEM_TOT (NSTAGE * STAGEB)   // 81920

// hi/lo halves in ONE array: [hi | lo], lo at constant element offset
#define XLO   (NTOK * DD)
#define W1LO  (NBANK * HH * DD)
#define W2LO  (NBANK * DD * HH)
#define HSLO  (NTOK * SS * HH)
#define HGLO  (NTOK * GG * HH)

__device__ __align__(16) __half gxA[2 * NTOK * DD];
__device__ __align__(16) __half gw1A[2 * NBANK * HH * DD];   // [bank][N][K]
__device__ __align__(16) __half gw2A[2 * NBANK * DD * HH];
__device__ __align__(16) __half gh1sA[2 * NTOK * SS * HH];
__device__ __align__(16) __half gh1gA[2 * NTOK * GG * HH];
__device__ __align__(16) float g_outs[NTOK * SS * DD], g_outg[NTOK * GG * DD];
__device__ int g_gid[NTOK], g_perm[NTOK];
__device__ int g_tile_group[MAXTILES], g_tile_m0[MAXTILES], g_tile_end[MAXTILES], g_ntiles;

// ---------------- PTX helpers ------------------------------------------------
__device__ __forceinline__ void cp16(uint32_t d, const void* s, bool v) {
    int sz = v ? 16 : 0;
    asm volatile("cp.async.cg.shared.global [%0], [%1], 16, %2;" :: "r"(d), "l"(s), "r"(sz));
}
#define CPC() asm volatile("cp.async.commit_group;")
#define CPW(N) asm volatile("cp.async.wait_group %0;" :: "n"(N))
#define LDSM4(r, a) asm volatile("ldmatrix.sync.aligned.m8n8.x4.shared.b16 {%0,%1,%2,%3}, [%4];" \
    : "=r"((r)[0]), "=r"((r)[1]), "=r"((r)[2]), "=r"((r)[3]) : "r"(a))
#define MMA16(d, a, b) asm volatile( \
    "mma.sync.aligned.m16n8k16.row.col.f32.f16.f16.f32 " \
    "{%0,%1,%2,%3}, {%4,%5,%6,%7}, {%8,%9}, {%0,%1,%2,%3};" \
    : "+f"((d)[0]), "+f"((d)[1]), "+f"((d)[2]), "+f"((d)[3]) \
    : "r"((a)[0]), "r"((a)[1]), "r"((a)[2]), "r"((a)[3]), "r"((b)[0]), "r"((b)[1]))

// ---------------- fused prep: cvt_x | cvt_w L1 | cvt_w L2 | token sort -------
#define CVX_BLK 2048                       // NTOK*DD/4/256
#define CVW1_BLK ((DD / 64) * (HH / 64) * NBANK)   // 1792
#define CVW2_BLK ((HH / 64) * (DD / 64) * NBANK)   // 1792
#define PRE_BLKS (CVX_BLK + CVW1_BLK + CVW2_BLK + 1)

__device__ __forceinline__ void cvt_w_tile(const float* __restrict__ sp,
                                           __half2* __restrict__ dst, int WLO2,
                                           int Kd, int Nd, int z, int k0, int n0,
                                           float (*s)[65], int t) {
    int r = t >> 4, c4 = (t & 15) * 4;
#pragma unroll
    for (int i = 0; i < 4; i++) {
        float4 v = *reinterpret_cast<const float4*>(
            sp + (size_t)(k0 + r + 16 * i) * Nd + n0 + c4);
        s[r + 16 * i][c4 + 0] = v.x;
        s[r + 16 * i][c4 + 1] = v.y;
        s[r + 16 * i][c4 + 2] = v.z;
        s[r + 16 * i][c4 + 3] = v.w;
    }
    __syncthreads();
    int tx = t & 31, ny = t >> 5;
#pragma unroll
    for (int i = 0; i < 8; i++) {
        int nl = ny * 8 + i;
        float v0 = s[2 * tx][nl], v1 = s[2 * tx + 1][nl];
        __half h0 = __float2half_rn(v0), h1 = __float2half_rn(v1);
        __half2 H; H.x = h0; H.y = h1;
        __half2 L;
        L.x = __float2half_rn(v0 - __half2float(h0));
        L.y = __float2half_rn(v1 - __half2float(h1));
        size_t o = (((size_t)z * Nd + n0 + nl) * Kd + k0) / 2 + tx;
        dst[o] = H;
        dst[WLO2 + o] = L;
    }
}

__global__ void __launch_bounds__(256)
k_pre(const float4* __restrict__ x,
      const float* __restrict__ Ws1, const float* __restrict__ Wg1,
      const float* __restrict__ Ws2, const float* __restrict__ Wg2,
      const int* __restrict__ nti, const int* __restrict__ e2g) {
    __shared__ float s[64][65];
    __shared__ int cnt[NGR], st[NGR], cur[NGR];
    const int b = blockIdx.x;
    const int t = threadIdx.x;

    if (b < CVX_BLK) {
        // ---- split x -> fp16 hi/lo ----
        int i = b * 256 + t;
        float4 v = x[i];
        __half h0 = __float2half_rn(v.x), h1 = __float2half_rn(v.y);
        __half h2 = __float2half_rn(v.z), h3 = __float2half_rn(v.w);
        __half2 H0; H0.x = h0; H0.y = h1;
        __half2 H1; H1.x = h2; H1.y = h3;
        __half2 L0, L1;
        L0.x = __float2half_rn(v.x - __half2float(h0));
        L0.y = __float2half_rn(v.y - __half2float(h1));
        L1.x = __float2half_rn(v.z - __half2float(h2));
        L1.y = __float2half_rn(v.w - __half2float(h3));
        __half2* hp = reinterpret_cast<__half2*>(gxA);
        hp[2 * i] = H0;
        hp[2 * i + 1] = H1;
        hp[XLO / 2 + 2 * i] = L0;
        hp[XLO / 2 + 2 * i + 1] = L1;
    } else if (b < CVX_BLK + CVW1_BLK) {
        // ---- layer-1 weights: Kd=DD, Nd=HH ----
        int lin = b - CVX_BLK;
        int z = lin / ((DD / 64) * (HH / 64));
        int rem = lin % ((DD / 64) * (HH / 64));
        int k0 = (rem % (DD / 64)) * 64, n0 = (rem / (DD / 64)) * 64;
        const float* sp = (z < SS) ? Ws1 + (size_t)z * DD * HH
                                   : Wg1 + (size_t)(z - SS) * DD * HH;
        cvt_w_tile(sp, reinterpret_cast<__half2*>(gw1A), W1LO / 2, DD, HH, z, k0, n0, s, t);
    } else if (b < CVX_BLK + CVW1_BLK + CVW2_BLK) {
        // ---- layer-2 weights: Kd=HH, Nd=DD ----
        int lin = b - CVX_BLK - CVW1_BLK;
        int z = lin / ((HH / 64) * (DD / 64));
        int rem = lin % ((HH / 64) * (DD / 64));
        int k0 = (rem % (HH / 64)) * 64, n0 = (rem / (HH / 64)) * 64;
        const float* sp = (z < SS) ? Ws2 + (size_t)z * HH * DD
                                   : Wg2 + (size_t)(z - SS) * HH * DD;
        cvt_w_tile(sp, reinterpret_cast<__half2*>(gw2A), W2LO / 2, HH, DD, z, k0, n0, s, t);
    } else {
        // ---- group ids + counting sort + tile table (single block) ----
        if (t < NGR) cnt[t] = 0;
        __syncthreads();
        for (int n = t; n < NTOK; n += 256) {
            int v = nti[n]; v = v < 0 ? 0 : (v > NEVT - 1 ? NEVT - 1 : v);
            int g = e2g[v]; g_gid[n] = g; atomicAdd(&cnt[g], 1);
        }
        __syncthreads();
        if (t == 0) {
            int acc = 0, ntl = 0;
            for (int g = 0; g < NGR; g++) {
                st[g] = acc; int c = cnt[g];
                for (int m0 = acc; m0 < acc + c; m0 += BM) {
                    g_tile_group[ntl] = g; g_tile_m0[ntl] = m0; g_tile_end[ntl] = acc + c; ntl++;
                }
                acc += c;
            }
            g_ntiles = ntl;
            for (int g = 0; g < NGR; g++) cur[g] = st[g];
        }
        __syncthreads();
        for (int n = t; n < NTOK; n += 256) {
            int pos = atomicAdd(&cur[g_gid[n]], 1);
            g_perm[pos] = n;
        }
    }
}

// ---------------- fp16x3 tensor GEMM (R13 mainloop, merged arrays) -----------
// D += Ah*Bh + Ah*Bl + Al*Bh  (fp32 accum; lo*lo ~2^-24, dropped)
template <int LAYER>
__global__ void __launch_bounds__(256)
k_mma(const float* __restrict__ bias_s, const float* __restrict__ bias_g) {
    const int KTOT = (LAYER == 1) ? DD : HH;
    const int WLO = (LAYER == 1) ? W1LO : W2LO;
    bool grouped;
    int m0, mend, g = 0;
    if ((int)blockIdx.x < NSHT) {
        grouped = false; m0 = blockIdx.x * BM; mend = NTOK;
    } else {
        grouped = true;
        int tile = blockIdx.x - NSHT;
        if (tile >= g_ntiles) return;
        g = g_tile_group[tile]; m0 = g_tile_m0[tile]; mend = g_tile_end[tile];
    }
    const int colstart = blockIdx.y * BN;

    extern __shared__ char dsm[];
    const uint32_t base = (uint32_t)__cvta_generic_to_shared(dsm);

    const int tid = threadIdx.x;
    const int lane = tid & 31;
    const int warp = tid >> 5;
    const int wm = warp >> 2;
    const int wn = warp & 3;

    int bias_off, seg;
    const __half* wH;
    const float* bias;
    if (LAYER == 1) {
        seg = colstart >> 10;
        int bank = grouped ? (SS + g * GG + seg) : seg;
        wH = gw1A + ((size_t)bank * HH + (colstart & (HH - 1))) * DD;
        bias_off = grouped ? g * (GG * HH) + colstart : colstart;
    } else {
        seg = colstart >> 9;
        int bank = grouped ? (SS + g * GG + seg) : seg;
        wH = gw2A + ((size_t)bank * DD + (colstart & (DD - 1))) * HH;
        bias_off = grouped ? g * (GG * DD) + colstart : colstart;
    }
    bias = grouped ? bias_g : bias_s;

    const int r0 = tid >> 2, r1 = 64 + (tid >> 2);
    const uint32_t cb = (uint32_t)(tid & 3) * 16;
    const uint32_t o0 = (uint32_t)r0 * LDHB + cb, o1 = (uint32_t)r1 * LDHB + cb;
    const int kadd = (tid & 3) * 8;

    const __half *pa0, *pa1;
    size_t aLo;
    bool v0 = true, v1 = true;
    {
        int p0 = m0 + r0, p1 = m0 + r1;
        if (LAYER == 1) {
            aLo = XLO;
            if (!grouped) {
                pa0 = gxA + (size_t)p0 * DD;
                pa1 = gxA + (size_t)p1 * DD;
            } else {
                v0 = p0 < mend; v1 = p1 < mend;
                pa0 = gxA + (size_t)(v0 ? g_perm[p0] : 0) * DD;
                pa1 = gxA + (size_t)(v1 ? g_perm[p1] : 0) * DD;
            }
        } else {
            if (!grouped) {
                aLo = HSLO;
                pa0 = gh1sA + (size_t)p0 * (SS * HH) + seg * HH;
                pa1 = gh1sA + (size_t)p1 * (SS * HH) + seg * HH;
            } else {
                aLo = HGLO;
                v0 = p0 < mend; v1 = p1 < mend;
                pa0 = gh1gA + (size_t)(v0 ? p0 : 0) * (GG * HH) + seg * HH;
                pa1 = gh1gA + (size_t)(v1 ? p1 : 0) * (GG * HH) + seg * HH;
            }
        }
    }
    const __half* pb0 = wH + (size_t)r0 * KTOT;
    const __half* pb1 = wH + (size_t)r1 * KTOT;

    // stage layout: [Ah][Al][Bh][Bl]
    auto load = [&](int buf, int it) {
        uint32_t sB = base + buf * STAGEB;
        int ke = it * BK + kadd;
        const __half* a0 = pa0 + ke;
        const __half* a1 = pa1 + ke;
        const __half* b0 = pb0 + ke;
        const __half* b1 = pb1 + ke;
        cp16(sB + o0, a0, v0);
        cp16(sB + o1, a1, v1);
        cp16(sB + ARRB + o0, a0 + aLo, v0);
        cp16(sB + ARRB + o1, a1 + aLo, v1);
        cp16(sB + 2 * ARRB + o0, b0, true);
        cp16(sB + 2 * ARRB + o1, b1, true);
        cp16(sB + 3 * ARRB + o0, b0 + WLO, true);
        cp16(sB + 3 * ARRB + o1, b1 + WLO, true);
        CPC();
    };

    float d[4][4][4];
#pragma unroll
    for (int i = 0; i < 4; i++)
#pragma unroll
        for (int j = 0; j < 4; j++)
#pragma unroll
            for (int q = 0; q < 4; q++) d[i][j][q] = 0.f;

    const int NIT = KTOT / BK;
    load(0, 0);

    for (int it = 0; it < NIT; it++) {
        const int buf = it & 1;
        if (it + 1 < NIT) { load(buf ^ 1, it + 1); CPW(1); }
        else CPW(0);
        __syncthreads();
        const uint32_t sB = base + buf * STAGEB;

#pragma unroll
        for (int ks = 0; ks < 2; ks++) {
            const uint32_t colb = (uint32_t)((ks * 16 + ((lane >> 4) << 3)) << 1);
            uint32_t ah[4][4], al[4][4], bh[4][2], bl[4][2];
#pragma unroll
            for (int mt = 0; mt < 4; mt++) {
                uint32_t addr = sB + (uint32_t)(wm * 64 + mt * 16 + (lane & 15)) * LDHB + colb;
                LDSM4(ah[mt], addr);
                LDSM4(al[mt], addr + ARRB);
            }
#pragma unroll
            for (int np = 0; np < 2; np++) {
                uint32_t addr = sB + 2 * ARRB
                              + (uint32_t)(wn * 32 + np * 16 + (lane & 15)) * LDHB + colb;
                uint32_t q[4];
                LDSM4(q, addr);
                bh[np * 2][0] = q[0]; bh[np * 2][1] = q[2];
                bh[np * 2 + 1][0] = q[1]; bh[np * 2 + 1][1] = q[3];
                LDSM4(q, addr + ARRB);
                bl[np * 2][0] = q[0]; bl[np * 2][1] = q[2];
                bl[np * 2 + 1][0] = q[1]; bl[np * 2 + 1][1] = q[3];
            }
#pragma unroll
            for (int mt = 0; mt < 4; mt++)
#pragma unroll
                for (int nt = 0; nt < 4; nt++) MMA16(d[mt][nt], ah[mt], bh[nt]);
#pragma unroll
            for (int mt = 0; mt < 4; mt++)
#pragma unroll
                for (int nt = 0; nt < 4; nt++) MMA16(d[mt][nt], ah[mt], bl[nt]);
#pragma unroll
            for (int mt = 0; mt < 4; mt++)
#pragma unroll
                for (int nt = 0; nt < 4; nt++) MMA16(d[mt][nt], al[mt], bh[nt]);
        }
        __syncthreads();
    }

    // ---- epilogue ----
    float bb0[4], bb1[4];
#pragma unroll
    for (int nt = 0; nt < 4; nt++) {
        int cbx = wn * 32 + nt * 8 + 2 * (lane & 3);
        bb0[nt] = bias[bias_off + cbx];
        bb1[nt] = bias[bias_off + cbx + 1];
    }

#pragma unroll
    for (int mt = 0; mt < 4; mt++) {
#pragma unroll
        for (int half = 0; half < 2; half++) {
            int p = m0 + wm * 64 + mt * 16 + (lane >> 2) + half * 8;
            if (grouped && p >= mend) continue;
            if (LAYER == 1) {
                __half* dh;
                size_t hLo;
                if (!grouped) {
                    dh = gh1sA + (size_t)p * (SS * HH) + colstart;
                    hLo = HSLO;
                } else {
                    dh = gh1gA + (size_t)p * (GG * HH) + colstart;
                    hLo = HGLO;
                }
#pragma unroll
                for (int nt = 0; nt < 4; nt++) {
                    int cbx = wn * 32 + nt * 8 + 2 * (lane & 3);
                    float u0 = d[mt][nt][half * 2 + 0] + bb0[nt];
                    float u1 = d[mt][nt][half * 2 + 1] + bb1[nt];
                    u0 = u0 > 0.f ? u0 : 0.f;
                    u1 = u1 > 0.f ? u1 : 0.f;
                    __half h0 = __float2half_rn(u0), h1 = __float2half_rn(u1);
                    __half2 H; H.x = h0; H.y = h1;
                    __half2 L;
                    L.x = __float2half_rn(u0 - __half2float(h0));
                    L.y = __float2half_rn(u1 - __half2float(h1));
                    *reinterpret_cast<__half2*>(dh + cbx) = H;
                    *reinterpret_cast<__half2*>(dh + hLo + cbx) = L;
                }
            } else {
                float* dst = (!grouped) ? g_outs + (size_t)p * (SS * DD) + colstart
                                        : g_outg + (size_t)g_perm[p] * (GG * DD) + colstart;
#pragma unroll
                for (int nt = 0; nt < 4; nt++) {
                    int cbx = wn * 32 + nt * 8 + 2 * (lane & 3);
                    float u0 = d[mt][nt][half * 2 + 0] + bb0[nt];
                    float u1 = d[mt][nt][half * 2 + 1] + bb1[nt];
                    *reinterpret_cast<float2*>(dst + cbx) = make_float2(u0, u1);
                }
            }
        }
    }
}

// ---------------- gate + combine ---------------------------------------------
__global__ void k_gate(const float* __restrict__ x, const float* __restrict__ cond_emb,
                       const float* __restrict__ gate_W, const float* __restrict__ gate_b,
                       float* __restrict__ out) {
    const int n = blockIdx.x;
    const int FD = DD + CC;
    __shared__ float gx[DD + CC], lg[KK * 4], w[KK * 4];
    const int t = threadIdx.x;
    const float* xr = x + (size_t)n * DD;
    for (int i = t; i < DD; i += 128) gx[i] = xr[i];
    if (t < CC) gx[DD + t] = cond_emb[g_gid[n] * CC + t];
    __syncthreads();
    const int warp = t >> 5, lane = t & 31, p0 = warp * 3;
    float s0 = 0.f, s1 = 0.f, s2 = 0.f;
    for (int f = lane; f < FD; f += 32) {
        float xv = gx[f];
        int p;
        p = p0 + 0; s0 = fmaf(xv, gate_W[((p >> 2) * FD + f) * 4 + (p & 3)], s0);
        p = p0 + 1; s1 = fmaf(xv, gate_W[((p >> 2) * FD + f) * 4 + (p & 3)], s1);
        p = p0 + 2; s2 = fmaf(xv, gate_W[((p >> 2) * FD + f) * 4 + (p & 3)], s2);
    }
#pragma unroll
    for (int o = 16; o > 0; o >>= 1) {
        s0 += __shfl_down_sync(0xffffffffu, s0, o);
        s1 += __shfl_down_sync(0xffffffffu, s1, o);
        s2 += __shfl_down_sync(0xffffffffu, s2, o);
    }
    if (lane == 0) {
        lg[p0 + 0] = s0 + gate_b[p0 + 0];
        lg[p0 + 1] = s1 + gate_b[p0 + 1];
        lg[p0 + 2] = s2 + gate_b[p0 + 2];
    }
    __syncthreads();
    if (t < KK) {
        float l0 = lg[t * 4], l1 = lg[t * 4 + 1], l2 = lg[t * 4 + 2], l3 = lg[t * 4 + 3];
        float m = fmaxf(fmaxf(l0, l1), fmaxf(l2, l3));
        float e0 = expf(l0 - m), e1 = expf(l1 - m), e2 = expf(l2 - m), e3 = expf(l3 - m);
        float inv = 1.f / (e0 + e1 + e2 + e3);
        w[t * 4] = e0 * inv; w[t * 4 + 1] = e1 * inv;
        w[t * 4 + 2] = e2 * inv; w[t * 4 + 3] = e3 * inv;
    }
    __syncthreads();
    const float4* so4 = reinterpret_cast<const float4*>(g_outs + (size_t)n * (SS * DD));
    const float4* go4 = reinterpret_cast<const float4*>(g_outg + (size_t)n * (GG * DD));
    {
        float4 e0 = so4[t], e1 = so4[DD / 4 + t], e2 = go4[t], e3 = go4[DD / 4 + t];
#pragma unroll
        for (int k = 0; k < KK; k++) {
            float w0 = w[k * 4], w1 = w[k * 4 + 1], w2 = w[k * 4 + 2], w3 = w[k * 4 + 3];
            float4 r;
            r.x = w0 * e0.x + w1 * e1.x + w2 * e2.x + w3 * e3.x;
            r.y = w0 * e0.y + w1 * e1.y + w2 * e2.y + w3 * e3.y;
            r.z = w0 * e0.z + w1 * e1.z + w2 * e2.z + w3 * e3.z;
            r.w = w0 * e0.w + w1 * e1.w + w2 * e2.w + w3 * e3.w;
            reinterpret_cast<float4*>(out)[((size_t)k * NTOK + n) * (DD / 4) + t] = r;
        }
    }
}

// ---------------- launch ------------------------------------------------------
extern "C" void kernel_launch(void* const* d_in, const int* in_sizes, int n_in,
                              void* d_out, int out_size) {
    const float* x   = (const float*)d_in[0];
    const int* nti   = (const int*)d_in[1];
    const int* e2g   = (const int*)d_in[2];
    const float* Ws1 = (const float*)d_in[3];
    const float* bs1 = (const float*)d_in[4];
    const float* Ws2 = (const float*)d_in[5];
    const float* bs2 = (const float*)d_in[6];
    const float* Wg1 = (const float*)d_in[7];
    const float* bg1 = (const float*)d_in[8];
    const float* Wg2 = (const float*)d_in[9];
    const float* bg2 = (const float*)d_in[10];
    const float* cemb = (const float*)d_in[11];
    const float* gW  = (const float*)d_in[12];
    const float* gb  = (const float*)d_in[13];
    float* out = (float*)d_out;

    cudaFuncSetAttribute(k_mma<1>, cudaFuncAttributeMaxDynamicSharedMemorySize, SMEM_TOT);
    cudaFuncSetAttribute(k_mma<2>, cudaFuncAttributeMaxDynamicSharedMemorySize, SMEM_TOT);

    k_pre<<<PRE_BLKS, 256>>>((const float4*)x, Ws1, Wg1, Ws2, Wg2, nti, e2g);
    k_mma<1><<<dim3(NSHT + MAXTILES, (SS * HH) / BN), 256, SMEM_TOT>>>(bs1, bg1);
    k_mma<2><<<dim3(NSHT + MAXTILES, (SS * DD) / BN), 256, SMEM_TOT>>>(bs2, bg2);
    k_gate<<<NTOK, 128>>>(x, cemb, gW, gb, out);
}